// round 4
// baseline (speedup 1.0000x reference)
#include <cuda_runtime.h>

#define NR   8192   // rows
#define CIN  512
#define CI   128
#define NSEG 64
#define SEG  128    // NR / NSEG

// ---- scratch (device globals; no allocation allowed) ----
__device__ float d_u[CIN], d_v[CIN];
__device__ float d_cc[2];                 // ca, cb
__device__ float d_a[NR], d_b[NR];
__device__ float d_g[NR * CI];            // 4 MB
__device__ float d_bs[NR];                // sorted b
__device__ int   d_si[NR];                // permutation
__device__ float d_T1[NSEG * CI], d_T2[NSEG * CI];
__device__ float d_O1[NSEG * CI], d_O2[NSEG * CI];
__device__ float d_P1[NR * CI], d_P2[NR * CI];   // 8.4 MB suffix sums

// K1: u = Wt @ w1, v = Wp @ w2, ca = bt.w1, cb = bp.w2   (1 block, 512 thr)
__global__ void k_uv(const float* __restrict__ Wt, const float* __restrict__ bt,
                     const float* __restrict__ Wp, const float* __restrict__ bp,
                     const float* __restrict__ wcat) {
    __shared__ float sw[2 * CI];
    __shared__ float red[2][CI];
    int t = threadIdx.x;
    if (t < 2 * CI) sw[t] = wcat[t];
    __syncthreads();
    float su = 0.f, sv = 0.f;
    #pragma unroll 8
    for (int o = 0; o < CI; o++) {
        su += Wt[t * CI + o] * sw[o];
        sv += Wp[t * CI + o] * sw[CI + o];
    }
    d_u[t] = su; d_v[t] = sv;
    if (t < CI) { red[0][t] = bt[t] * sw[t]; red[1][t] = bp[t] * sw[CI + t]; }
    __syncthreads();
    if (t < 2) {
        float s = 0.f;
        for (int o = 0; o < CI; o++) s += red[t][o];
        d_cc[t] = s;
    }
}

// K2: a[i] = x_i.u + ca, b[i] = x_i.v + cb   (warp per row; 1024 blocks x 256)
__global__ void __launch_bounds__(256) k_ab(const float* __restrict__ x) {
    __shared__ float su[CIN], sv[CIN];
    int tid = threadIdx.x;
    for (int i = tid; i < CIN; i += 256) { su[i] = d_u[i]; sv[i] = d_v[i]; }
    __syncthreads();
    int warp = tid >> 5, lane = tid & 31;
    int row = blockIdx.x * 8 + warp;
    const float* xr = x + row * CIN;
    float sa = 0.f, sb = 0.f;
    #pragma unroll
    for (int m = 0; m < 16; m++) {
        float xv = xr[lane + 32 * m];
        sa += xv * su[lane + 32 * m];
        sb += xv * sv[lane + 32 * m];
    }
    #pragma unroll
    for (int o = 16; o > 0; o >>= 1) {
        sa += __shfl_xor_sync(0xFFFFFFFFu, sa, o);
        sb += __shfl_xor_sync(0xFFFFFFFFu, sb, o);
    }
    if (lane == 0) { d_a[row] = sa + d_cc[0]; d_b[row] = sb + d_cc[1]; }
}

// K3: g = x @ Wg + bg   (fp32 tiled GEMM, 128 blocks x 256, 64-row tiles)
__global__ void __launch_bounds__(256, 1) k_g(const float* __restrict__ x,
                                              const float* __restrict__ Wg,
                                              const float* __restrict__ bg) {
    __shared__ float xs[32][65];     // padded: conflict-free transposed store
    __shared__ float ws[32][CI];
    int tid = threadIdx.x;
    int tx = tid & 31, ty = tid >> 5;       // tx: 4 cols, ty: 8 rows
    int bm = blockIdx.x * 64;
    float acc[8][4];
    #pragma unroll
    for (int r = 0; r < 8; r++)
        #pragma unroll
        for (int c = 0; c < 4; c++) acc[r][c] = 0.f;

    int lr = tid >> 2, lkq = (tid & 3) * 8; // x-tile load mapping

    for (int k0 = 0; k0 < CIN; k0 += 32) {
        const float* xp = x + (bm + lr) * CIN + k0 + lkq;
        float4 xa = *(const float4*)xp;
        float4 xb = *(const float4*)(xp + 4);
        xs[lkq + 0][lr] = xa.x; xs[lkq + 1][lr] = xa.y;
        xs[lkq + 2][lr] = xa.z; xs[lkq + 3][lr] = xa.w;
        xs[lkq + 4][lr] = xb.x; xs[lkq + 5][lr] = xb.y;
        xs[lkq + 6][lr] = xb.z; xs[lkq + 7][lr] = xb.w;
        #pragma unroll
        for (int s = 0; s < 4; s++) {
            float4 wv = *(const float4*)(Wg + (k0 + ty + 8 * s) * CI + tx * 4);
            *(float4*)&ws[ty + 8 * s][tx * 4] = wv;
        }
        __syncthreads();
        #pragma unroll
        for (int kk = 0; kk < 32; kk++) {
            float4 wv = *(const float4*)&ws[kk][tx * 4];
            float xv[8];
            #pragma unroll
            for (int rr = 0; rr < 8; rr++) xv[rr] = xs[kk][ty * 8 + rr];
            #pragma unroll
            for (int rr = 0; rr < 8; rr++) {
                acc[rr][0] += xv[rr] * wv.x;
                acc[rr][1] += xv[rr] * wv.y;
                acc[rr][2] += xv[rr] * wv.z;
                acc[rr][3] += xv[rr] * wv.w;
            }
        }
        __syncthreads();
    }
    float4 bgv = *(const float4*)(bg + tx * 4);
    #pragma unroll
    for (int rr = 0; rr < 8; rr++) {
        int row = bm + ty * 8 + rr;
        float4 o;
        o.x = acc[rr][0] + bgv.x; o.y = acc[rr][1] + bgv.y;
        o.z = acc[rr][2] + bgv.z; o.w = acc[rr][3] + bgv.w;
        *(float4*)&d_g[row * CI + tx * 4] = o;
    }
}

// K4: rank-sort b (count-smaller with index tie-break).  256 blocks x 512 thr,
//     32 j's per block, 16 partial scanners of 512 elems each.
__global__ void __launch_bounds__(512) k_rank() {
    __shared__ float sb[NR];            // 32 KB
    __shared__ int part[16][32];
    int tid = threadIdx.x;
    for (int i = tid; i < NR; i += 512) sb[i] = d_b[i];
    __syncthreads();
    int p = tid >> 5, jl = tid & 31;
    int j = blockIdx.x * 32 + jl;
    float bj = sb[j];
    int cnt = 0;
    const float4* sb4 = reinterpret_cast<const float4*>(sb);
    int b4 = p * 128;                   // 128 float4 = 512 elements
    #pragma unroll 4
    for (int m = 0; m < 128; m++) {
        float4 q = sb4[b4 + m];
        int mi = (b4 + m) * 4;
        cnt += (q.x < bj) || (q.x == bj && (mi    ) < j);
        cnt += (q.y < bj) || (q.y == bj && (mi + 1) < j);
        cnt += (q.z < bj) || (q.z == bj && (mi + 2) < j);
        cnt += (q.w < bj) || (q.w == bj && (mi + 3) < j);
    }
    part[p][jl] = cnt;
    __syncthreads();
    if (tid < 32) {
        int rank = 0;
        #pragma unroll
        for (int pp = 0; pp < 16; pp++) rank += part[pp][tid];
        int jj = blockIdx.x * 32 + tid;
        d_bs[rank] = sb[jj];
        d_si[rank] = jj;
    }
}

// K5: per-segment totals of g[perm] and b_sorted*g[perm]   (64 blocks x 128)
__global__ void __launch_bounds__(SEG) k_segsum() {
    __shared__ int ssi[SEG];
    __shared__ float sbs[SEG];
    int s = blockIdx.x, c = threadIdx.x;
    ssi[c] = d_si[s * SEG + c];
    sbs[c] = d_bs[s * SEG + c];
    __syncthreads();
    float t1 = 0.f, t2 = 0.f;
    #pragma unroll 8
    for (int m = 0; m < SEG; m++) {
        float gv = d_g[ssi[m] * CI + c];
        t1 += gv;
        t2 += sbs[m] * gv;
    }
    d_T1[s * CI + c] = t1; d_T2[s * CI + c] = t2;
}

// K6: exclusive suffix offsets across segments   (1 block x 128)
__global__ void k_off() {
    int c = threadIdx.x;
    float r1 = 0.f, r2 = 0.f;
    for (int s = NSEG - 1; s >= 0; s--) {
        d_O1[s * CI + c] = r1; d_O2[s * CI + c] = r2;
        r1 += d_T1[s * CI + c]; r2 += d_T2[s * CI + c];
    }
}

// K7: full suffix sums P1[k] = sum_{m>=k} g[perm(m)], P2 with b weight
__global__ void __launch_bounds__(SEG) k_psum() {
    __shared__ int ssi[SEG];
    __shared__ float sbs[SEG];
    int s = blockIdx.x, c = threadIdx.x;
    ssi[c] = d_si[s * SEG + c];
    sbs[c] = d_bs[s * SEG + c];
    __syncthreads();
    float a1 = d_O1[s * CI + c], a2 = d_O2[s * CI + c];
    #pragma unroll 4
    for (int m = SEG - 1; m >= 0; m--) {
        float gv = d_g[ssi[m] * CI + c];
        a1 += gv;
        a2 += sbs[m] * gv;
        d_P1[(s * SEG + m) * CI + c] = a1;
        d_P2[(s * SEG + m) * CI + c] = a2;
    }
}

// K8: z_i = (a_i * P1[k_i] + P2[k_i]) / N, k_i via binary search  (4096 x 256)
__global__ void __launch_bounds__(256) k_out(float* __restrict__ z) {
    __shared__ int sk[2];
    __shared__ float sa[2];
    int tid = threadIdx.x;
    int half = tid >> 7, c = tid & 127;
    int row = blockIdx.x * 2 + half;
    if (c == 0) {
        float av = d_a[row];
        float t = -av;
        int lo = 0, hi = NR;
        while (lo < hi) {
            int mid = (lo + hi) >> 1;
            if (__ldg(&d_bs[mid]) > t) hi = mid; else lo = mid + 1;
        }
        sk[half] = lo; sa[half] = av;
    }
    __syncthreads();
    int k = sk[half];
    float o = 0.f;
    if (k < NR)
        o = (sa[half] * d_P1[k * CI + c] + d_P2[k * CI + c]) * (1.0f / (float)NR);
    z[row * CI + c] = o;
}

extern "C" void kernel_launch(void* const* d_in, const int* in_sizes, int n_in,
                              void* d_out, int out_size) {
    const float* x    = (const float*)d_in[0];
    const float* Wg   = (const float*)d_in[1];
    const float* bg   = (const float*)d_in[2];
    const float* Wt   = (const float*)d_in[3];
    const float* bt   = (const float*)d_in[4];
    const float* Wp   = (const float*)d_in[5];
    const float* bp   = (const float*)d_in[6];
    const float* wcat = (const float*)d_in[7];
    float* z = (float*)d_out;

    k_uv<<<1, 512>>>(Wt, bt, Wp, bp, wcat);
    k_ab<<<NR / 8, 256>>>(x);
    k_g<<<NR / 64, 256>>>(x, Wg, bg);
    k_rank<<<NR / 32, 512>>>();
    k_segsum<<<NSEG, SEG>>>();
    k_off<<<1, CI>>>();
    k_psum<<<NSEG, SEG>>>();
    k_out<<<NR / 2, 256>>>(z);
}

// round 5
// speedup vs baseline: 1.3930x; 1.3930x over previous
#include <cuda_runtime.h>

#define NR   8192   // rows
#define CIN  512
#define CI   128
#define NSEG 256
#define SEG  32     // NR / NSEG

// ---- scratch (device globals; no allocation allowed) ----
__device__ float d_u[CIN], d_v[CIN];
__device__ float d_cc[2];                 // ca, cb
__device__ float d_a[NR], d_b[NR];
__device__ float d_g[NR * CI];            // 4 MB
__device__ float d_bs[NR];                // sorted b
__device__ int   d_si[NR];                // permutation
__device__ float d_T1[NSEG * CI], d_T2[NSEG * CI];
__device__ float d_O1[NSEG * CI], d_O2[NSEG * CI];
__device__ float d_P1[NR * CI], d_P2[NR * CI];   // 8.4 MB suffix sums

// packed f32x2 FMA (Blackwell): d = a*b + c elementwise on {lo,hi}
#define FMA_F32X2(d, a, b, c) \
    asm("fma.rn.f32x2 %0, %1, %2, %3;" : "=l"(d) : "l"(a), "l"(b), "l"(c))
#define PACK_F32X2(out, lo, hi) \
    asm("mov.b64 %0, {%1, %2};" : "=l"(out) : "f"(lo), "f"(hi))

__device__ __forceinline__ float f2lo(unsigned long long v) {
    return __uint_as_float((unsigned)(v & 0xFFFFFFFFull));
}
__device__ __forceinline__ float f2hi(unsigned long long v) {
    return __uint_as_float((unsigned)(v >> 32));
}

// K1: u = Wt @ w1, v = Wp @ w2  (grid 65 x 256: blocks 0-63 warp-per-t; block 64: cc)
__global__ void __launch_bounds__(256) k_uv(const float* __restrict__ Wt,
                                            const float* __restrict__ bt,
                                            const float* __restrict__ Wp,
                                            const float* __restrict__ bp,
                                            const float* __restrict__ wcat) {
    __shared__ float sw[2 * CI];
    int tid = threadIdx.x;
    sw[tid] = wcat[tid];
    __syncthreads();
    if (blockIdx.x < 64) {
        int warp = tid >> 5, lane = tid & 31;
        int t = blockIdx.x * 8 + warp;
        float su = 0.f, sv = 0.f;
        #pragma unroll
        for (int m = 0; m < 4; m++) {
            int o = lane + 32 * m;
            su += Wt[t * CI + o] * sw[o];
            sv += Wp[t * CI + o] * sw[CI + o];
        }
        #pragma unroll
        for (int o = 16; o > 0; o >>= 1) {
            su += __shfl_xor_sync(0xFFFFFFFFu, su, o);
            sv += __shfl_xor_sync(0xFFFFFFFFu, sv, o);
        }
        if (lane == 0) { d_u[t] = su; d_v[t] = sv; }
    } else {
        __shared__ float redA[4], redB[4];
        int warp = tid >> 5, lane = tid & 31;
        float ra = 0.f, rb = 0.f;
        if (tid < CI) {
            ra = bt[tid] * sw[tid];
            rb = bp[tid] * sw[CI + tid];
        }
        #pragma unroll
        for (int o = 16; o > 0; o >>= 1) {
            ra += __shfl_xor_sync(0xFFFFFFFFu, ra, o);
            rb += __shfl_xor_sync(0xFFFFFFFFu, rb, o);
        }
        if (lane == 0 && warp < 4) { redA[warp] = ra; redB[warp] = rb; }
        __syncthreads();
        if (tid == 0) {
            d_cc[0] = redA[0] + redA[1] + redA[2] + redA[3];
            d_cc[1] = redB[0] + redB[1] + redB[2] + redB[3];
        }
    }
}

// K2: a[i] = x_i.u + ca, b[i] = x_i.v + cb   (warp per row; 1024 blocks x 256)
__global__ void __launch_bounds__(256) k_ab(const float* __restrict__ x) {
    __shared__ float su[CIN], sv[CIN];
    int tid = threadIdx.x;
    for (int i = tid; i < CIN; i += 256) { su[i] = d_u[i]; sv[i] = d_v[i]; }
    __syncthreads();
    int warp = tid >> 5, lane = tid & 31;
    int row = blockIdx.x * 8 + warp;
    const float4* xr4 = (const float4*)(x + row * CIN);
    const float4* su4 = (const float4*)su;
    const float4* sv4 = (const float4*)sv;
    float sa = 0.f, sb = 0.f;
    #pragma unroll
    for (int m = 0; m < 4; m++) {
        int j = lane + 32 * m;
        float4 xv = xr4[j];
        float4 uu = su4[j];
        float4 vv = sv4[j];
        sa += xv.x * uu.x + xv.y * uu.y + xv.z * uu.z + xv.w * uu.w;
        sb += xv.x * vv.x + xv.y * vv.y + xv.z * vv.z + xv.w * vv.w;
    }
    #pragma unroll
    for (int o = 16; o > 0; o >>= 1) {
        sa += __shfl_xor_sync(0xFFFFFFFFu, sa, o);
        sb += __shfl_xor_sync(0xFFFFFFFFu, sb, o);
    }
    if (lane == 0) { d_a[row] = sa + d_cc[0]; d_b[row] = sb + d_cc[1]; }
}

// K3: g = x @ Wg + bg   (fp32x2 tiled GEMM, 128 blocks x 256, 64x128 tiles)
// Thread (tx = tid&31 -> 4 cols at tx*4, ty = tid>>5 -> 8 rows at ty*8).
// Rows processed as 4 packed pairs via FFMA2; x-pairs come free from the
// 64-bit halves of broadcast LDS.128 on xs (stride 72 keeps 16B alignment).
__global__ void __launch_bounds__(256, 1) k_g(const float* __restrict__ x,
                                              const float* __restrict__ Wg,
                                              const float* __restrict__ bg) {
    __shared__ float xs[32][72];     // transposed x tile: xs[k][row]
    __shared__ float ws[32][CI];
    int tid = threadIdx.x;
    int tx = tid & 31, ty = tid >> 5;
    int bm = blockIdx.x * 64;

    unsigned long long acc2[4][4];   // [rowpair][col]
    #pragma unroll
    for (int p = 0; p < 4; p++)
        #pragma unroll
        for (int c = 0; c < 4; c++) acc2[p][c] = 0ull;

    int lr = tid >> 2, lkq = (tid & 3) * 8; // x-tile load mapping

    for (int k0 = 0; k0 < CIN; k0 += 32) {
        const float* xp = x + (bm + lr) * CIN + k0 + lkq;
        float4 xa = *(const float4*)xp;
        float4 xb = *(const float4*)(xp + 4);
        xs[lkq + 0][lr] = xa.x; xs[lkq + 1][lr] = xa.y;
        xs[lkq + 2][lr] = xa.z; xs[lkq + 3][lr] = xa.w;
        xs[lkq + 4][lr] = xb.x; xs[lkq + 5][lr] = xb.y;
        xs[lkq + 6][lr] = xb.z; xs[lkq + 7][lr] = xb.w;
        #pragma unroll
        for (int s = 0; s < 4; s++) {
            float4 wv = *(const float4*)(Wg + (k0 + ty + 8 * s) * CI + tx * 4);
            *(float4*)&ws[ty + 8 * s][tx * 4] = wv;
        }
        __syncthreads();
        #pragma unroll
        for (int kk = 0; kk < 32; kk++) {
            // 8 row values as 4 packed pairs (broadcast LDS.128, 16B aligned)
            ulonglong2 xp0 = *(const ulonglong2*)&xs[kk][ty * 8];
            ulonglong2 xp1 = *(const ulonglong2*)&xs[kk][ty * 8 + 4];
            float4 wv = *(const float4*)&ws[kk][tx * 4];
            unsigned long long w0, w1, w2, w3;
            PACK_F32X2(w0, wv.x, wv.x);
            PACK_F32X2(w1, wv.y, wv.y);
            PACK_F32X2(w2, wv.z, wv.z);
            PACK_F32X2(w3, wv.w, wv.w);
            FMA_F32X2(acc2[0][0], xp0.x, w0, acc2[0][0]);
            FMA_F32X2(acc2[0][1], xp0.x, w1, acc2[0][1]);
            FMA_F32X2(acc2[0][2], xp0.x, w2, acc2[0][2]);
            FMA_F32X2(acc2[0][3], xp0.x, w3, acc2[0][3]);
            FMA_F32X2(acc2[1][0], xp0.y, w0, acc2[1][0]);
            FMA_F32X2(acc2[1][1], xp0.y, w1, acc2[1][1]);
            FMA_F32X2(acc2[1][2], xp0.y, w2, acc2[1][2]);
            FMA_F32X2(acc2[1][3], xp0.y, w3, acc2[1][3]);
            FMA_F32X2(acc2[2][0], xp1.x, w0, acc2[2][0]);
            FMA_F32X2(acc2[2][1], xp1.x, w1, acc2[2][1]);
            FMA_F32X2(acc2[2][2], xp1.x, w2, acc2[2][2]);
            FMA_F32X2(acc2[2][3], xp1.x, w3, acc2[2][3]);
            FMA_F32X2(acc2[3][0], xp1.y, w0, acc2[3][0]);
            FMA_F32X2(acc2[3][1], xp1.y, w1, acc2[3][1]);
            FMA_F32X2(acc2[3][2], xp1.y, w2, acc2[3][2]);
            FMA_F32X2(acc2[3][3], xp1.y, w3, acc2[3][3]);
        }
        __syncthreads();
    }
    float4 bgv = *(const float4*)(bg + tx * 4);
    #pragma unroll
    for (int p = 0; p < 4; p++) {
        int row0 = bm + ty * 8 + 2 * p;
        float4 o0, o1;
        o0.x = f2lo(acc2[p][0]) + bgv.x; o0.y = f2lo(acc2[p][1]) + bgv.y;
        o0.z = f2lo(acc2[p][2]) + bgv.z; o0.w = f2lo(acc2[p][3]) + bgv.w;
        o1.x = f2hi(acc2[p][0]) + bgv.x; o1.y = f2hi(acc2[p][1]) + bgv.y;
        o1.z = f2hi(acc2[p][2]) + bgv.z; o1.w = f2hi(acc2[p][3]) + bgv.w;
        *(float4*)&d_g[row0 * CI + tx * 4] = o0;
        *(float4*)&d_g[(row0 + 1) * CI + tx * 4] = o1;
    }
}

// K4: rank-sort b via 64-bit keys (order-preserving float map << 32 | index).
// One u64 compare per pair replaces the float+tiebreak combo (~5 -> ~3 ops).
// 256 blocks x 512 thr; 64 KB dynamic smem keys; 16 scanners of 512 keys.
__global__ void __launch_bounds__(512) k_rank() {
    extern __shared__ unsigned long long sk[];   // NR keys = 64 KB
    __shared__ int part[16][32];
    int tid = threadIdx.x;
    for (int i = tid; i < NR; i += 512) {
        unsigned int ib = __float_as_uint(d_b[i]);
        unsigned int ord = ib ^ ((unsigned)(((int)ib) >> 31) | 0x80000000u);
        sk[i] = ((unsigned long long)ord << 32) | (unsigned)i;
    }
    __syncthreads();
    int p = tid >> 5, jl = tid & 31;
    int j = blockIdx.x * 32 + jl;
    unsigned long long kj = sk[j];
    int cnt = 0;
    const ulonglong2* sk2 = reinterpret_cast<const ulonglong2*>(sk);
    int base = p * 256;                 // 256 ulonglong2 = 512 keys
    #pragma unroll 8
    for (int m = 0; m < 256; m++) {
        ulonglong2 q = sk2[base + m];
        cnt += (q.x < kj);
        cnt += (q.y < kj);
    }
    part[p][jl] = cnt;
    __syncthreads();
    if (tid < 32) {
        int rank = 0;
        #pragma unroll
        for (int pp = 0; pp < 16; pp++) rank += part[pp][tid];
        int jj = blockIdx.x * 32 + tid;
        d_bs[rank] = d_b[jj];
        d_si[rank] = jj;
    }
}

// K5: per-segment totals of g[perm] and b_sorted*g[perm]   (256 blocks x 128)
__global__ void __launch_bounds__(CI) k_segsum() {
    __shared__ int ssi[SEG];
    __shared__ float sbs[SEG];
    int s = blockIdx.x, c = threadIdx.x;
    if (c < SEG) {
        ssi[c] = d_si[s * SEG + c];
        sbs[c] = d_bs[s * SEG + c];
    }
    __syncthreads();
    float t1 = 0.f, t2 = 0.f;
    #pragma unroll 8
    for (int m = 0; m < SEG; m++) {
        float gv = d_g[ssi[m] * CI + c];
        t1 += gv;
        t2 += sbs[m] * gv;
    }
    d_T1[s * CI + c] = t1; d_T2[s * CI + c] = t2;
}

// K6: exclusive suffix offsets across segments   (1 block x 128)
__global__ void k_off() {
    int c = threadIdx.x;
    float r1 = 0.f, r2 = 0.f;
    for (int s = NSEG - 1; s >= 0; s--) {
        d_O1[s * CI + c] = r1; d_O2[s * CI + c] = r2;
        r1 += d_T1[s * CI + c]; r2 += d_T2[s * CI + c];
    }
}

// K7: full suffix sums P1[k] = sum_{m>=k} g[perm(m)], P2 with b weight
__global__ void __launch_bounds__(CI) k_psum() {
    __shared__ int ssi[SEG];
    __shared__ float sbs[SEG];
    int s = blockIdx.x, c = threadIdx.x;
    if (c < SEG) {
        ssi[c] = d_si[s * SEG + c];
        sbs[c] = d_bs[s * SEG + c];
    }
    __syncthreads();
    float a1 = d_O1[s * CI + c], a2 = d_O2[s * CI + c];
    #pragma unroll 4
    for (int m = SEG - 1; m >= 0; m--) {
        float gv = d_g[ssi[m] * CI + c];
        a1 += gv;
        a2 += sbs[m] * gv;
        d_P1[(s * SEG + m) * CI + c] = a1;
        d_P2[(s * SEG + m) * CI + c] = a2;
    }
}

// K8: z_i = (a_i * P1[k_i] + P2[k_i]) / N, k_i via binary search  (4096 x 256)
__global__ void __launch_bounds__(256) k_out(float* __restrict__ z) {
    __shared__ int sk_[2];
    __shared__ float sa[2];
    int tid = threadIdx.x;
    int half = tid >> 7, c = tid & 127;
    int row = blockIdx.x * 2 + half;
    if (c == 0) {
        float av = d_a[row];
        float t = -av;
        int lo = 0, hi = NR;
        while (lo < hi) {
            int mid = (lo + hi) >> 1;
            if (__ldg(&d_bs[mid]) > t) hi = mid; else lo = mid + 1;
        }
        sk_[half] = lo; sa[half] = av;
    }
    __syncthreads();
    int k = sk_[half];
    float o = 0.f;
    if (k < NR)
        o = (sa[half] * d_P1[k * CI + c] + d_P2[k * CI + c]) * (1.0f / (float)NR);
    z[row * CI + c] = o;
}

extern "C" void kernel_launch(void* const* d_in, const int* in_sizes, int n_in,
                              void* d_out, int out_size) {
    const float* x    = (const float*)d_in[0];
    const float* Wg   = (const float*)d_in[1];
    const float* bg   = (const float*)d_in[2];
    const float* Wt   = (const float*)d_in[3];
    const float* bt   = (const float*)d_in[4];
    const float* Wp   = (const float*)d_in[5];
    const float* bp   = (const float*)d_in[6];
    const float* wcat = (const float*)d_in[7];
    float* z = (float*)d_out;

    // idempotent; host-side attribute set is capture-safe
    cudaFuncSetAttribute(k_rank, cudaFuncAttributeMaxDynamicSharedMemorySize,
                         NR * sizeof(unsigned long long));

    k_uv<<<65, 256>>>(Wt, bt, Wp, bp, wcat);
    k_ab<<<NR / 8, 256>>>(x);
    k_g<<<NR / 64, 256>>>(x, Wg, bg);
    k_rank<<<NR / 32, 512, NR * sizeof(unsigned long long)>>>();
    k_segsum<<<NSEG, CI>>>();
    k_off<<<1, CI>>>();
    k_psum<<<NSEG, CI>>>();
    k_out<<<NR / 2, 256>>>(z);
}

// round 6
// speedup vs baseline: 1.9276x; 1.3837x over previous
#include <cuda_runtime.h>

#define NR   8192   // rows
#define CIN  512
#define CI   128
#define NB   4096   // value buckets
#define GRP  16     // buckets per group
#define NG   (NB / GRP)   // 256 groups

// ---- scratch (device globals; no allocation allowed) ----
__device__ float d_u[CIN], d_v[CIN];
__device__ float d_cc[2];                 // ca, cb
__device__ float d_a[NR], d_b[NR];
__device__ float d_g[NR * CI];            // 4 MB
__device__ float d_bsv[NR];               // b values in bucketed order
__device__ int   d_si[NR];                // bucketed permutation
__device__ int   d_bstart[NB + 1];
__device__ unsigned d_bmin_ord, d_bmax_ord;
__device__ float d_brange[2];             // lo, scale
__device__ float d_T1[NG * CI], d_T2[NG * CI];
__device__ float d_O1[NG * CI], d_O2[NG * CI];
__device__ float d_SB1[(NB + 1) * CI];    // bucket-boundary suffix sums (2.1 MB)
__device__ float d_SB2[(NB + 1) * CI];

// packed f32x2 FMA (Blackwell)
#define FMA_F32X2(d, a, b, c) \
    asm("fma.rn.f32x2 %0, %1, %2, %3;" : "=l"(d) : "l"(a), "l"(b), "l"(c))
#define PACK_F32X2(out, lo, hi) \
    asm("mov.b64 %0, {%1, %2};" : "=l"(out) : "f"(lo), "f"(hi))

__device__ __forceinline__ float f2lo(unsigned long long v) {
    return __uint_as_float((unsigned)(v & 0xFFFFFFFFull));
}
__device__ __forceinline__ float f2hi(unsigned long long v) {
    return __uint_as_float((unsigned)(v >> 32));
}
__device__ __forceinline__ unsigned ford(float f) {           // monotone float->uint
    unsigned b = __float_as_uint(f);
    return b ^ ((unsigned)(((int)b) >> 31) | 0x80000000u);
}
__device__ __forceinline__ float forddec(unsigned e) {
    return __uint_as_float((e & 0x80000000u) ? (e ^ 0x80000000u) : ~e);
}
__device__ __forceinline__ int bidx(float v, float lo, float scale) {
    int i = (int)((v - lo) * scale);                          // trunc: monotone
    return max(0, min(NB - 1, i));
}

// K1: u = Wt @ w1, v = Wp @ w2  (blocks 0-63 warp-per-t; block 64: cc + range init)
__global__ void __launch_bounds__(256) k_uv(const float* __restrict__ Wt,
                                            const float* __restrict__ bt,
                                            const float* __restrict__ Wp,
                                            const float* __restrict__ bp,
                                            const float* __restrict__ wcat) {
    __shared__ float sw[2 * CI];
    int tid = threadIdx.x;
    sw[tid] = wcat[tid];
    __syncthreads();
    if (blockIdx.x < 64) {
        int warp = tid >> 5, lane = tid & 31;
        int t = blockIdx.x * 8 + warp;
        float su = 0.f, sv = 0.f;
        #pragma unroll
        for (int m = 0; m < 4; m++) {
            int o = lane + 32 * m;
            su += Wt[t * CI + o] * sw[o];
            sv += Wp[t * CI + o] * sw[CI + o];
        }
        #pragma unroll
        for (int o = 16; o > 0; o >>= 1) {
            su += __shfl_xor_sync(0xFFFFFFFFu, su, o);
            sv += __shfl_xor_sync(0xFFFFFFFFu, sv, o);
        }
        if (lane == 0) { d_u[t] = su; d_v[t] = sv; }
    } else {
        __shared__ float redA[4], redB[4];
        int warp = tid >> 5, lane = tid & 31;
        float ra = 0.f, rb = 0.f;
        if (tid < CI) {
            ra = bt[tid] * sw[tid];
            rb = bp[tid] * sw[CI + tid];
        }
        #pragma unroll
        for (int o = 16; o > 0; o >>= 1) {
            ra += __shfl_xor_sync(0xFFFFFFFFu, ra, o);
            rb += __shfl_xor_sync(0xFFFFFFFFu, rb, o);
        }
        if (lane == 0 && warp < 4) { redA[warp] = ra; redB[warp] = rb; }
        __syncthreads();
        if (tid == 0) {
            d_cc[0] = redA[0] + redA[1] + redA[2] + redA[3];
            d_cc[1] = redB[0] + redB[1] + redB[2] + redB[3];
            d_bmin_ord = 0xFFFFFFFFu;      // re-init every launch (graph replay)
            d_bmax_ord = 0u;
        }
    }
}

// K2: a[i], b[i] + block min/max of b   (warp per row; 1024 blocks x 256)
__global__ void __launch_bounds__(256) k_ab(const float* __restrict__ x) {
    __shared__ float su[CIN], sv[CIN];
    __shared__ float sbv8[8];
    int tid = threadIdx.x;
    for (int i = tid; i < CIN; i += 256) { su[i] = d_u[i]; sv[i] = d_v[i]; }
    __syncthreads();
    int warp = tid >> 5, lane = tid & 31;
    int row = blockIdx.x * 8 + warp;
    const float4* xr4 = (const float4*)(x + row * CIN);
    const float4* su4 = (const float4*)su;
    const float4* sv4 = (const float4*)sv;
    float sa = 0.f, sb = 0.f;
    #pragma unroll
    for (int m = 0; m < 4; m++) {
        int j = lane + 32 * m;
        float4 xv = xr4[j];
        float4 uu = su4[j];
        float4 vv = sv4[j];
        sa += xv.x * uu.x + xv.y * uu.y + xv.z * uu.z + xv.w * uu.w;
        sb += xv.x * vv.x + xv.y * vv.y + xv.z * vv.z + xv.w * vv.w;
    }
    #pragma unroll
    for (int o = 16; o > 0; o >>= 1) {
        sa += __shfl_xor_sync(0xFFFFFFFFu, sa, o);
        sb += __shfl_xor_sync(0xFFFFFFFFu, sb, o);
    }
    if (lane == 0) {
        float bvv = sb + d_cc[1];
        d_a[row] = sa + d_cc[0];
        d_b[row] = bvv;
        sbv8[warp] = bvv;
    }
    __syncthreads();
    if (tid == 0) {
        float mn = sbv8[0], mx = sbv8[0];
        #pragma unroll
        for (int q = 1; q < 8; q++) { mn = fminf(mn, sbv8[q]); mx = fmaxf(mx, sbv8[q]); }
        atomicMin(&d_bmin_ord, ford(mn));
        atomicMax(&d_bmax_ord, ford(mx));
    }
}

// K3: g = x @ Wg + bg   (fp32x2 tiled GEMM, 128 blocks x 256, 64x128 tiles)
__global__ void __launch_bounds__(256, 1) k_g(const float* __restrict__ x,
                                              const float* __restrict__ Wg,
                                              const float* __restrict__ bg) {
    __shared__ float xs[32][72];
    __shared__ float ws[32][CI];
    int tid = threadIdx.x;
    int tx = tid & 31, ty = tid >> 5;
    int bm = blockIdx.x * 64;

    unsigned long long acc2[4][4];
    #pragma unroll
    for (int p = 0; p < 4; p++)
        #pragma unroll
        for (int c = 0; c < 4; c++) acc2[p][c] = 0ull;

    int lr = tid >> 2, lkq = (tid & 3) * 8;

    for (int k0 = 0; k0 < CIN; k0 += 32) {
        const float* xp = x + (bm + lr) * CIN + k0 + lkq;
        float4 xa = *(const float4*)xp;
        float4 xb = *(const float4*)(xp + 4);
        xs[lkq + 0][lr] = xa.x; xs[lkq + 1][lr] = xa.y;
        xs[lkq + 2][lr] = xa.z; xs[lkq + 3][lr] = xa.w;
        xs[lkq + 4][lr] = xb.x; xs[lkq + 5][lr] = xb.y;
        xs[lkq + 6][lr] = xb.z; xs[lkq + 7][lr] = xb.w;
        #pragma unroll
        for (int s = 0; s < 4; s++) {
            float4 wv = *(const float4*)(Wg + (k0 + ty + 8 * s) * CI + tx * 4);
            *(float4*)&ws[ty + 8 * s][tx * 4] = wv;
        }
        __syncthreads();
        #pragma unroll
        for (int kk = 0; kk < 32; kk++) {
            ulonglong2 xp0 = *(const ulonglong2*)&xs[kk][ty * 8];
            ulonglong2 xp1 = *(const ulonglong2*)&xs[kk][ty * 8 + 4];
            float4 wv = *(const float4*)&ws[kk][tx * 4];
            unsigned long long w0, w1, w2, w3;
            PACK_F32X2(w0, wv.x, wv.x);
            PACK_F32X2(w1, wv.y, wv.y);
            PACK_F32X2(w2, wv.z, wv.z);
            PACK_F32X2(w3, wv.w, wv.w);
            FMA_F32X2(acc2[0][0], xp0.x, w0, acc2[0][0]);
            FMA_F32X2(acc2[0][1], xp0.x, w1, acc2[0][1]);
            FMA_F32X2(acc2[0][2], xp0.x, w2, acc2[0][2]);
            FMA_F32X2(acc2[0][3], xp0.x, w3, acc2[0][3]);
            FMA_F32X2(acc2[1][0], xp0.y, w0, acc2[1][0]);
            FMA_F32X2(acc2[1][1], xp0.y, w1, acc2[1][1]);
            FMA_F32X2(acc2[1][2], xp0.y, w2, acc2[1][2]);
            FMA_F32X2(acc2[1][3], xp0.y, w3, acc2[1][3]);
            FMA_F32X2(acc2[2][0], xp1.x, w0, acc2[2][0]);
            FMA_F32X2(acc2[2][1], xp1.x, w1, acc2[2][1]);
            FMA_F32X2(acc2[2][2], xp1.x, w2, acc2[2][2]);
            FMA_F32X2(acc2[2][3], xp1.x, w3, acc2[2][3]);
            FMA_F32X2(acc2[3][0], xp1.y, w0, acc2[3][0]);
            FMA_F32X2(acc2[3][1], xp1.y, w1, acc2[3][1]);
            FMA_F32X2(acc2[3][2], xp1.y, w2, acc2[3][2]);
            FMA_F32X2(acc2[3][3], xp1.y, w3, acc2[3][3]);
        }
        __syncthreads();
    }
    float4 bgv = *(const float4*)(bg + tx * 4);
    #pragma unroll
    for (int p = 0; p < 4; p++) {
        int row0 = bm + ty * 8 + 2 * p;
        float4 o0, o1;
        o0.x = f2lo(acc2[p][0]) + bgv.x; o0.y = f2lo(acc2[p][1]) + bgv.y;
        o0.z = f2lo(acc2[p][2]) + bgv.z; o0.w = f2lo(acc2[p][3]) + bgv.w;
        o1.x = f2hi(acc2[p][0]) + bgv.x; o1.y = f2hi(acc2[p][1]) + bgv.y;
        o1.z = f2hi(acc2[p][2]) + bgv.z; o1.w = f2hi(acc2[p][3]) + bgv.w;
        *(float4*)&d_g[row0 * CI + tx * 4] = o0;
        *(float4*)&d_g[(row0 + 1) * CI + tx * 4] = o1;
    }
}

// K4: counting-sort b into NB value buckets (1 block, 1024 threads).
// Replaces the O(N^2) rank kernel: histogram -> scan -> scatter.
__global__ void __launch_bounds__(1024) k_bucket() {
    __shared__ int hist[NB];           // 16 KB
    __shared__ int scanbuf[1024];
    __shared__ float sls[2];           // lo, scale
    int tid = threadIdx.x;
    #pragma unroll
    for (int q = 0; q < NB / 1024; q++) hist[tid + 1024 * q] = 0;
    if (tid == 0) {
        float lo = forddec(d_bmin_ord);
        float hi = forddec(d_bmax_ord);
        float d = hi - lo;
        float scale = (d > 0.f) ? ((float)NB / d) : 0.f;
        sls[0] = lo; sls[1] = scale;
        d_brange[0] = lo; d_brange[1] = scale;
    }
    __syncthreads();
    float lo = sls[0], scale = sls[1];
    for (int j = tid; j < NR; j += 1024)
        atomicAdd(&hist[bidx(d_b[j], lo, scale)], 1);
    __syncthreads();
    int h0 = hist[4 * tid], h1 = hist[4 * tid + 1];
    int h2 = hist[4 * tid + 2], h3 = hist[4 * tid + 3];
    int tot = h0 + h1 + h2 + h3;
    scanbuf[tid] = tot;
    __syncthreads();
    #pragma unroll
    for (int off = 1; off < 1024; off <<= 1) {
        int v = (tid >= off) ? scanbuf[tid - off] : 0;
        __syncthreads();
        scanbuf[tid] += v;
        __syncthreads();
    }
    int excl = scanbuf[tid] - tot;
    d_bstart[4 * tid]     = excl;
    d_bstart[4 * tid + 1] = excl + h0;
    d_bstart[4 * tid + 2] = excl + h0 + h1;
    d_bstart[4 * tid + 3] = excl + h0 + h1 + h2;
    hist[4 * tid]     = excl;          // running counters for scatter
    hist[4 * tid + 1] = excl + h0;
    hist[4 * tid + 2] = excl + h0 + h1;
    hist[4 * tid + 3] = excl + h0 + h1 + h2;
    if (tid == 0) d_bstart[NB] = NR;
    __syncthreads();
    for (int j = tid; j < NR; j += 1024) {
        float bv = d_b[j];
        int pos = atomicAdd(&hist[bidx(bv, lo, scale)], 1);
        d_si[pos] = j;
        d_bsv[pos] = bv;
    }
}

// K5: per-group (16 buckets) totals of g and b*g   (NG blocks x 128)
__global__ void __launch_bounds__(CI) k_segsum() {
    __shared__ int ssi[CI];
    __shared__ float sbv[CI];
    int g = blockIdx.x, c = threadIdx.x;
    int pstart = d_bstart[g * GRP];
    int pend   = d_bstart[g * GRP + GRP];
    float t1 = 0.f, t2 = 0.f;
    for (int base = pstart; base < pend; base += CI) {
        int nchunk = min(CI, pend - base);
        if (c < nchunk) { ssi[c] = d_si[base + c]; sbv[c] = d_bsv[base + c]; }
        __syncthreads();
        for (int m = 0; m < nchunk; m++) {
            float gv = d_g[ssi[m] * CI + c];
            t1 += gv;
            t2 += sbv[m] * gv;
        }
        __syncthreads();
    }
    d_T1[g * CI + c] = t1; d_T2[g * CI + c] = t2;
}

// K6: exclusive suffix offsets across groups (1 block x 128, chunked prefetch)
__global__ void __launch_bounds__(CI) k_off() {
    int c = threadIdx.x;
    float r1 = 0.f, r2 = 0.f;
    for (int s0 = NG - 8; s0 >= 0; s0 -= 8) {
        float t1[8], t2[8];
        #pragma unroll
        for (int q = 0; q < 8; q++) {
            t1[q] = d_T1[(s0 + q) * CI + c];
            t2[q] = d_T2[(s0 + q) * CI + c];
        }
        #pragma unroll
        for (int q = 7; q >= 0; q--) {
            d_O1[(s0 + q) * CI + c] = r1;
            d_O2[(s0 + q) * CI + c] = r2;
            r1 += t1[q]; r2 += t2[q];
        }
    }
}

// K7: bucket-boundary suffix sums SB[bk] = sum over buckets >= bk  (NG blocks x 128)
__global__ void __launch_bounds__(CI) k_psum() {
    int g = blockIdx.x, c = threadIdx.x;
    float a1 = d_O1[g * CI + c], a2 = d_O2[g * CI + c];
    for (int bk = GRP - 1; bk >= 0; bk--) {
        int gb = g * GRP + bk;
        d_SB1[(gb + 1) * CI + c] = a1;
        d_SB2[(gb + 1) * CI + c] = a2;
        int ps = d_bstart[gb], pe = d_bstart[gb + 1];
        for (int pos = ps; pos < pe; pos++) {
            int j = d_si[pos];
            float bv = d_bsv[pos];
            float gv = d_g[j * CI + c];
            a1 += gv;
            a2 += bv * gv;
        }
    }
}

// K8: z_i = (a_i*S1 + S2)/N; S = bucket suffix + exact boundary-bucket members
__global__ void __launch_bounds__(256) k_out(float* __restrict__ z) {
    int tid = threadIdx.x;
    int half = tid >> 7, c = tid & 127;
    int row = blockIdx.x * 2 + half;
    float av = d_a[row];
    float t = -av;
    float lo = d_brange[0], scale = d_brange[1];
    int bt = bidx(t, lo, scale);
    float s1 = d_SB1[(bt + 1) * CI + c];
    float s2 = d_SB2[(bt + 1) * CI + c];
    int ps = d_bstart[bt], pe = d_bstart[bt + 1];
    for (int pos = ps; pos < pe; pos++) {
        float bv = d_bsv[pos];
        if (bv > t) {
            float gv = d_g[d_si[pos] * CI + c];
            s1 += gv;
            s2 += bv * gv;
        }
    }
    z[row * CI + c] = (av * s1 + s2) * (1.0f / (float)NR);
}

extern "C" void kernel_launch(void* const* d_in, const int* in_sizes, int n_in,
                              void* d_out, int out_size) {
    const float* x    = (const float*)d_in[0];
    const float* Wg   = (const float*)d_in[1];
    const float* bg   = (const float*)d_in[2];
    const float* Wt   = (const float*)d_in[3];
    const float* bt   = (const float*)d_in[4];
    const float* Wp   = (const float*)d_in[5];
    const float* bp   = (const float*)d_in[6];
    const float* wcat = (const float*)d_in[7];
    float* z = (float*)d_out;

    k_uv<<<65, 256>>>(Wt, bt, Wp, bp, wcat);
    k_ab<<<NR / 8, 256>>>(x);
    k_bucket<<<1, 1024>>>();
    k_g<<<NR / 64, 256>>>(x, Wg, bg);
    k_segsum<<<NG, CI>>>();
    k_off<<<1, CI>>>();
    k_psum<<<NG, CI>>>();
    k_out<<<NR / 2, 256>>>(z);
}